// round 1
// baseline (speedup 1.0000x reference)
#include <cuda_runtime.h>
#include <cstdint>

#define BATCH  16
#define NPTS   4096
#define NPT    1024
#define KNN    32
#define POSN   (BATCH*NPT*KNN)   // 524288 positions
#define NTILES (POSN/64)         // 8192

// ---------------- scratch (device globals; no allocations allowed) ----------------
__device__ int    g_knn[POSN];                       // neighbor index per position
__device__ float  g_y1[(size_t)POSN*64];             // layer1 pre-BN
__device__ float  g_y2[(size_t)POSN*64];             // layer2 pre-BN
__device__ float  g_y3[(size_t)POSN*128];            // layer3 pre-BN
__device__ double g_sum[3][128];
__device__ double g_sqs[3][128];
__device__ float  g_scale[3][128];
__device__ float  g_shift[3][128];

// ---------------- zero stats ----------------
__global__ void zero_stats_kernel() {
    int t = threadIdx.x;           // 384 threads
    g_sum[t >> 7][t & 127] = 0.0;
    g_sqs[t >> 7][t & 127] = 0.0;
}

// ---------------- farthest point sampling ----------------
// One block per batch, 1024 threads, 4 points per thread held in registers.
// Matches jnp exactly: centroid = xyz[farthest] at loop entry; output is the
// entering farthest; argmax tie-break = lowest index (packed key).
__global__ void fps_kernel(const float* __restrict__ xyz,
                           const int* __restrict__ initf,
                           float* __restrict__ newxyz) {
    __shared__ unsigned long long wk[32];
    __shared__ int s_far;
    __shared__ float s_cx, s_cy, s_cz;

    const int b = blockIdx.x, tid = threadIdx.x;
    const float* xb = xyz + (size_t)b * NPTS * 3;

    float px[4], py[4], pz[4], dist[4];
#pragma unroll
    for (int j = 0; j < 4; j++) {
        int p = tid + 1024 * j;
        px[j] = xb[3 * p + 0];
        py[j] = xb[3 * p + 1];
        pz[j] = xb[3 * p + 2];
        dist[j] = 1e10f;
    }
    if (tid == 0) s_far = initf[b];
    __syncthreads();
    {   // owner of initial farthest publishes centroid coords
        int f = s_far;
        if (tid == (f & 1023)) {
            int oj = f >> 10;
            s_cx = px[oj]; s_cy = py[oj]; s_cz = pz[oj];
        }
    }
    __syncthreads();

    for (int it = 0; it < NPT; it++) {
        float cx = s_cx, cy = s_cy, cz = s_cz;
        if (tid == 0) {
            float* o = newxyz + (size_t)(b * NPT + it) * 3;
            o[0] = cx; o[1] = cy; o[2] = cz;
        }
        unsigned long long best = 0ULL;
#pragma unroll
        for (int j = 0; j < 4; j++) {
            float dx = __fsub_rn(px[j], cx);
            float dy = __fsub_rn(py[j], cy);
            float dz = __fsub_rn(pz[j], cz);
            float d = __fadd_rn(__fadd_rn(__fmul_rn(dx, dx), __fmul_rn(dy, dy)),
                                __fmul_rn(dz, dz));
            dist[j] = fminf(dist[j], d);
            unsigned long long key =
                ((unsigned long long)__float_as_uint(dist[j]) << 32) |
                (unsigned)(0xFFFFFFFFu - (unsigned)(tid + 1024 * j));
            best = (key > best) ? key : best;
        }
#pragma unroll
        for (int o = 16; o; o >>= 1) {
            unsigned long long t = __shfl_xor_sync(0xFFFFFFFFu, best, o);
            if (t > best) best = t;
        }
        if ((tid & 31) == 0) wk[tid >> 5] = best;
        __syncthreads();
        if (tid < 32) {
            unsigned long long k = wk[tid];
#pragma unroll
            for (int o = 16; o; o >>= 1) {
                unsigned long long t = __shfl_xor_sync(0xFFFFFFFFu, k, o);
                if (t > k) k = t;
            }
            if (tid == 0) s_far = (int)(0xFFFFFFFFu - (unsigned)(k & 0xFFFFFFFFu));
        }
        __syncthreads();
        {
            int nf = s_far;
            if (tid == (nf & 1023)) {
                int oj = nf >> 10;
                s_cx = px[oj]; s_cy = py[oj]; s_cz = pz[oj];
            }
        }
        __syncthreads();
    }
}

// ---------------- kNN (top-33 smallest, drop self) ----------------
// One thread per query. Packed (dist_bits, idx) uint64 keys reproduce
// jnp stable argsort ordering exactly.
__global__ void knn_kernel(const float* __restrict__ newxyz) {
    __shared__ float qx[NPT], qy[NPT], qz[NPT];
    const int b = blockIdx.x >> 3;
    const int chunk = blockIdx.x & 7;
    const float* nb = newxyz + (size_t)b * NPT * 3;
    for (int i = threadIdx.x; i < NPT; i += 128) {
        qx[i] = nb[3 * i + 0];
        qy[i] = nb[3 * i + 1];
        qz[i] = nb[3 * i + 2];
    }
    __syncthreads();

    const int s = chunk * 128 + threadIdx.x;
    const float x = qx[s], y = qy[s], z = qz[s];

    unsigned long long heap[KNN + 1];
#pragma unroll
    for (int i = 0; i <= KNN; i++) heap[i] = ~0ULL;

    for (int j = 0; j < NPT; j++) {
        float dx = __fsub_rn(qx[j], x);
        float dy = __fsub_rn(qy[j], y);
        float dz = __fsub_rn(qz[j], z);
        float d = __fadd_rn(__fadd_rn(__fmul_rn(dx, dx), __fmul_rn(dy, dy)),
                            __fmul_rn(dz, dz));
        unsigned long long key =
            ((unsigned long long)__float_as_uint(d) << 32) | (unsigned)j;
        if (key < heap[KNN]) {
            int pos = KNN;
            while (pos > 0 && heap[pos - 1] > key) { heap[pos] = heap[pos - 1]; --pos; }
            heap[pos] = key;
        }
    }
    int* o = g_knn + (size_t)(b * NPT + s) * KNN;
#pragma unroll
    for (int k = 0; k < KNN; k++)
        o[k] = (int)(heap[k + 1] & 0xFFFFFFFFu);   // drop self (rank 0)
}

// ---------------- layer 1: grouped gather + 3->64 conv, accumulate stats ----------------
__global__ void layer1_kernel(const float* __restrict__ xyz,
                              const float* __restrict__ newxyz,
                              const float* __restrict__ W1,
                              const float* __restrict__ b1) {
    __shared__ float4 zs[64];
    __shared__ float red[256], red2[256];
    const int tid = threadIdx.x;
    const int c = tid & 63, q = tid >> 6;
    const float w0 = W1[c * 3 + 0], w1 = W1[c * 3 + 1], w2 = W1[c * 3 + 2];
    const float bb = b1[c];
    float s = 0.f, s2 = 0.f;

    for (int tile = blockIdx.x; tile < NTILES; tile += gridDim.x) {
        int pbase = tile * 64;
        if (tid < 64) {
            int pos = pbase + tid;
            int bs = pos >> 5;           // b*1024 + s
            int b = bs >> 10;
            int j = g_knn[pos];
            const float* xp = xyz + (size_t)(b * NPTS + j) * 3;
            const float* np = newxyz + (size_t)bs * 3;
            zs[tid] = make_float4(xp[0] - np[0], xp[1] - np[1], xp[2] - np[2], 0.f);
        }
        __syncthreads();
        float acc[16];
#pragma unroll
        for (int u = 0; u < 16; u++) {
            float4 zv = zs[q * 16 + u];
            acc[u] = fmaf(w0, zv.x, fmaf(w1, zv.y, fmaf(w2, zv.z, bb)));
        }
#pragma unroll
        for (int u = 0; u < 16; u++) {
            float v = acc[u];
            g_y1[(size_t)(pbase + q * 16 + u) * 64 + c] = v;
            s += v; s2 += v * v;
        }
        __syncthreads();
    }
    red[tid] = s; red2[tid] = s2;
    __syncthreads();
    if (tid < 128) { red[tid] += red[tid + 128]; red2[tid] += red2[tid + 128]; }
    __syncthreads();
    if (tid < 64) {
        atomicAdd(&g_sum[0][tid], (double)(red[tid] + red[tid + 64]));
        atomicAdd(&g_sqs[0][tid], (double)(red2[tid] + red2[tid + 64]));
    }
}

// ---------------- layers 2/3: apply prev-layer BN+ReLU on load, 64->CO GEMM ----------------
// W rows in registers; z tile in shared as float4 (4 channels) per position;
// all GEMM LDS.128 are warp-broadcast (same address) -> FMA-bound, not LDS-bound.
template <int CO>
__global__ void __launch_bounds__(256)
layer_kernel(const float* __restrict__ W, const float* __restrict__ bias) {
    constexpr int QP = (CO == 64) ? 16 : 32;   // positions per thread
    constexpr int PREV = (CO == 64) ? 0 : 1;
    constexpr int SELF = (CO == 64) ? 1 : 2;
    const float* yin = (CO == 64) ? g_y1 : g_y2;
    float* yout = (CO == 64) ? g_y2 : g_y3;

    __shared__ float4 zs[16 * 65];
    __shared__ float ssc[64], ssh[64];
    __shared__ float red[256], red2[256];

    const int tid = threadIdx.x;
    const int c = tid & (CO - 1);
    const int q = tid / CO;

    if (tid < 64) { ssc[tid] = g_scale[PREV][tid]; ssh[tid] = g_shift[PREV][tid]; }

    float w[64];
#pragma unroll
    for (int i = 0; i < 64; i++) w[i] = W[c * 64 + i];
    const float bb = bias[c];
    float s = 0.f, s2 = 0.f;
    __syncthreads();

    for (int tile = blockIdx.x; tile < NTILES; tile += gridDim.x) {
        int pbase = tile * 64;
#pragma unroll
        for (int r = 0; r < 4; r++) {
            int e = tid + 256 * r;
            int p = e >> 4, cq = e & 15;
            float4 v = *(const float4*)(yin + (size_t)(pbase + p) * 64 + cq * 4);
            v.x = fmaxf(fmaf(v.x, ssc[4 * cq + 0], ssh[4 * cq + 0]), 0.f);
            v.y = fmaxf(fmaf(v.y, ssc[4 * cq + 1], ssh[4 * cq + 1]), 0.f);
            v.z = fmaxf(fmaf(v.z, ssc[4 * cq + 2], ssh[4 * cq + 2]), 0.f);
            v.w = fmaxf(fmaf(v.w, ssc[4 * cq + 3], ssh[4 * cq + 3]), 0.f);
            zs[cq * 65 + p] = v;
        }
        __syncthreads();

        float acc[QP];
#pragma unroll
        for (int u = 0; u < QP; u++) acc[u] = bb;
#pragma unroll
        for (int cq = 0; cq < 16; cq++) {
#pragma unroll
            for (int u = 0; u < QP; u++) {
                float4 zv = zs[cq * 65 + q * QP + u];
                acc[u] = fmaf(w[4 * cq + 0], zv.x, acc[u]);
                acc[u] = fmaf(w[4 * cq + 1], zv.y, acc[u]);
                acc[u] = fmaf(w[4 * cq + 2], zv.z, acc[u]);
                acc[u] = fmaf(w[4 * cq + 3], zv.w, acc[u]);
            }
        }
#pragma unroll
        for (int u = 0; u < QP; u++) {
            float v = acc[u];
            yout[(size_t)(pbase + q * QP + u) * CO + c] = v;
            s += v; s2 += v * v;
        }
        __syncthreads();
    }

    red[tid] = s; red2[tid] = s2;
    __syncthreads();
    if (CO == 64) {
        if (tid < 128) { red[tid] += red[tid + 128]; red2[tid] += red2[tid + 128]; }
        __syncthreads();
        if (tid < 64) {
            atomicAdd(&g_sum[SELF][tid], (double)(red[tid] + red[tid + 64]));
            atomicAdd(&g_sqs[SELF][tid], (double)(red2[tid] + red2[tid + 64]));
        }
    } else {
        if (tid < 128) {
            atomicAdd(&g_sum[SELF][tid], (double)(red[tid] + red[tid + 128]));
            atomicAdd(&g_sqs[SELF][tid], (double)(red2[tid] + red2[tid + 128]));
        }
    }
}

// ---------------- BN finalize: scale/shift per channel ----------------
__global__ void finalize_kernel(int l, const float* __restrict__ g,
                                const float* __restrict__ be, int C) {
    int c = threadIdx.x;
    if (c < C) {
        double n = (double)POSN;
        double m = g_sum[l][c] / n;
        double v = g_sqs[l][c] / n - m * m;
        if (v < 0.0) v = 0.0;
        float sc = g[c] * rsqrtf((float)v + 1e-5f);
        g_scale[l][c] = sc;
        g_shift[l][c] = be[c] - (float)m * sc;
    }
}

// ---------------- BN3 + ReLU + max-pool over K, channel-major output ----------------
__global__ void pool_kernel(float* __restrict__ out) {
    __shared__ float t[128 * 33];
    const int blk = blockIdx.x;
    const int b = blk >> 5, st = blk & 31;        // 32 s-tiles of 32
    const int tid = threadIdx.x;
    const int c = tid & 127, sg = tid >> 7;
    const float sc = g_scale[2][c], sh = g_shift[2][c];

    for (int sl = sg; sl < 32; sl += 2) {
        int bs = b * NPT + st * 32 + sl;
        const float* base = g_y3 + (size_t)bs * KNN * 128 + c;
        float m = 0.f;                             // == max over relu'd values
#pragma unroll
        for (int k = 0; k < KNN; k++)
            m = fmaxf(m, fmaf(base[(size_t)k * 128], sc, sh));
        t[c * 33 + sl] = m;
    }
    __syncthreads();
#pragma unroll
    for (int r = 0; r < 16; r++) {
        int e = tid + 256 * r;
        int c2 = e >> 5, s2 = e & 31;
        out[(size_t)(b * 128 + c2) * NPT + st * 32 + s2] = t[c2 * 33 + s2];
    }
}

// ---------------- launch ----------------
extern "C" void kernel_launch(void* const* d_in, const int* in_sizes, int n_in,
                              void* d_out, int out_size) {
    const float* xyz   = (const float*)d_in[0];
    const int*   initf = (const int*)d_in[1];
    const float* W1 = (const float*)d_in[2];
    const float* b1 = (const float*)d_in[3];
    const float* g1 = (const float*)d_in[4];
    const float* be1 = (const float*)d_in[5];
    const float* W2 = (const float*)d_in[6];
    const float* b2 = (const float*)d_in[7];
    const float* g2 = (const float*)d_in[8];
    const float* be2 = (const float*)d_in[9];
    const float* W3 = (const float*)d_in[10];
    const float* b3 = (const float*)d_in[11];
    const float* g3 = (const float*)d_in[12];
    const float* be3 = (const float*)d_in[13];

    float* out = (float*)d_out;
    float* newxyz = out;                               // [16,1024,3]
    float* newpts = out + (size_t)BATCH * NPT * 3;     // [16,128,1024]

    zero_stats_kernel<<<1, 384>>>();
    fps_kernel<<<BATCH, 1024>>>(xyz, initf, newxyz);
    knn_kernel<<<BATCH * 8, 128>>>(newxyz);
    layer1_kernel<<<1024, 256>>>(xyz, newxyz, W1, b1);
    finalize_kernel<<<1, 128>>>(0, g1, be1, 64);
    layer_kernel<64><<<592, 256>>>(W2, b2);
    finalize_kernel<<<1, 128>>>(1, g2, be2, 64);
    layer_kernel<128><<<592, 256>>>(W3, b3);
    finalize_kernel<<<1, 128>>>(2, g3, be3, 128);
    pool_kernel<<<512, 256>>>(newpts);
}

// round 3
// speedup vs baseline: 4.1863x; 4.1863x over previous
#include <cuda_runtime.h>
#include <cstdint>

#define BATCH  16
#define NPTS   4096
#define NPT    1024
#define KNN    32
#define POSN   (BATCH*NPT*KNN)   // 524288 positions
#define NTILES (POSN/64)         // 8192

// ---------------- scratch (device globals; no allocations allowed) ----------------
__device__ int    g_knn[POSN];                        // neighbor index per position
__device__ float  g_y1[(size_t)64  * POSN];           // layer1 pre-BN, channel-major [64][POSN]
__device__ float  g_y2[(size_t)64  * POSN];           // layer2 pre-BN, channel-major
__device__ float  g_y3[(size_t)128 * POSN];           // layer3 pre-BN, channel-major
__device__ double g_sum[3][128];
__device__ double g_sqs[3][128];
__device__ float  g_scale[3][128];
__device__ float  g_shift[3][128];

// ---- f32x2 helpers (Blackwell packed fp32) ----
__device__ __forceinline__ unsigned long long f2pack(float a, float b) {
    unsigned long long v;
    asm("mov.b64 %0, {%1, %2};" : "=l"(v) : "f"(a), "f"(b));
    return v;
}
__device__ __forceinline__ void f2unpack(unsigned long long v, float& a, float& b) {
    asm("mov.b64 {%0, %1}, %2;" : "=f"(a), "=f"(b) : "l"(v));
}
#define FMA2(d, a, b, c) \
    asm("fma.rn.f32x2 %0, %1, %2, %3;" : "=l"(d) : "l"(a), "l"(b), "l"(c))

// ---------------- zero stats ----------------
__global__ void zero_stats_kernel() {
    int t = threadIdx.x;           // 384 threads
    g_sum[t >> 7][t & 127] = 0.0;
    g_sqs[t >> 7][t & 127] = 0.0;
}

// ---------------- farthest point sampling ----------------
// One block per batch, 256 threads, 16 points/thread in registers.
// Single __syncthreads per iteration: double-buffered warp partials, then every
// thread redundantly computes the final argmax (integer-deterministic).
// Distance arithmetic matches jnp exactly: sub, mul, (a+b)+c, min.
__global__ void fps_kernel(const float* __restrict__ xyz,
                           const int* __restrict__ initf,
                           float* __restrict__ newxyz) {
    __shared__ unsigned long long wk[2][8];

    const int b = blockIdx.x, tid = threadIdx.x;
    const int lane = tid & 31, w = tid >> 5;
    const float* xb = xyz + (size_t)b * NPTS * 3;

    float px[16], py[16], pz[16], dist[16];
#pragma unroll
    for (int j = 0; j < 16; j++) {
        int p = tid + 256 * j;
        px[j] = xb[3 * p + 0];
        py[j] = xb[3 * p + 1];
        pz[j] = xb[3 * p + 2];
        dist[j] = 1e10f;
    }
    int f = initf[b];
    __syncthreads();

    for (int it = 0; it < NPT; it++) {
        float cx = xb[3 * f + 0], cy = xb[3 * f + 1], cz = xb[3 * f + 2];
        if (tid == 0) {
            float* o = newxyz + (size_t)(b * NPT + it) * 3;
            o[0] = cx; o[1] = cy; o[2] = cz;
        }
        unsigned long long best = 0ULL;
#pragma unroll
        for (int j = 0; j < 16; j++) {
            float dx = __fsub_rn(px[j], cx);
            float dy = __fsub_rn(py[j], cy);
            float dz = __fsub_rn(pz[j], cz);
            float d = __fadd_rn(__fadd_rn(__fmul_rn(dx, dx), __fmul_rn(dy, dy)),
                                __fmul_rn(dz, dz));
            dist[j] = fminf(dist[j], d);
            unsigned long long key =
                ((unsigned long long)__float_as_uint(dist[j]) << 32) |
                (unsigned)(0xFFFFFFFFu - (unsigned)(tid + 256 * j));
            best = (key > best) ? key : best;
        }
#pragma unroll
        for (int o = 16; o; o >>= 1) {
            unsigned long long t = __shfl_xor_sync(0xFFFFFFFFu, best, o);
            if (t > best) best = t;
        }
        if (lane == 0) wk[it & 1][w] = best;
        __syncthreads();
        unsigned long long k = wk[it & 1][0];
#pragma unroll
        for (int i = 1; i < 8; i++) {
            unsigned long long t = wk[it & 1][i];
            if (t > k) k = t;
        }
        f = (int)(0xFFFFFFFFu - (unsigned)(k & 0xFFFFFFFFu));
    }
}

// ---------------- kNN (top-33 smallest, drop rank 0) ----------------
// Warp per query. Each lane: 32 candidates -> register bitonic sort (static
// indices, no local mem) -> sorted list to padded shared. 33-step warp-min
// merge with shfl+ballot reproduces jnp stable-argsort order exactly
// (keys = (dist_bits<<32)|idx).
__global__ void knn_kernel(const float* __restrict__ newxyz) {
    __shared__ float qx[NPT], qy[NPT], qz[NPT];
    __shared__ unsigned long long sl[128][33];   // padded: conflict-free

    const int tid = threadIdx.x, lane = tid & 31, w = tid >> 5;
    const int b = blockIdx.x >> 8;
    const int s = ((blockIdx.x & 255) << 2) | w;
    const float* nb = newxyz + (size_t)b * NPT * 3;

    for (int i = tid; i < NPT; i += 128) {
        qx[i] = nb[3 * i + 0];
        qy[i] = nb[3 * i + 1];
        qz[i] = nb[3 * i + 2];
    }
    __syncthreads();

    const float x = qx[s], y = qy[s], z = qz[s];

    unsigned long long r[32];
#pragma unroll
    for (int u = 0; u < 32; u++) {
        int j = lane + 32 * u;                    // consecutive lanes: no conflicts
        float dx = __fsub_rn(qx[j], x);
        float dy = __fsub_rn(qy[j], y);
        float dz = __fsub_rn(qz[j], z);
        float d = __fadd_rn(__fadd_rn(__fmul_rn(dx, dx), __fmul_rn(dy, dy)),
                            __fmul_rn(dz, dz));
        r[u] = ((unsigned long long)__float_as_uint(d) << 32) | (unsigned)j;
    }

    // bitonic sort (ascending), all static indexing -> stays in registers
#pragma unroll
    for (int k = 2; k <= 32; k <<= 1) {
#pragma unroll
        for (int j = k >> 1; j > 0; j >>= 1) {
#pragma unroll
            for (int i = 0; i < 32; i++) {
                int ixj = i ^ j;
                if (ixj > i) {
                    bool up = ((i & k) == 0);
                    unsigned long long a = r[i], bb = r[ixj];
                    if ((a > bb) == up) { r[i] = bb; r[ixj] = a; }
                }
            }
        }
    }

#pragma unroll
    for (int u = 0; u < 32; u++) sl[tid][u] = r[u];

    unsigned long long cand = r[0];
    int h = 1;
    int myidx = 0;
    for (int t = 0; t < 33; t++) {
        unsigned long long m = cand;
#pragma unroll
        for (int o = 16; o; o >>= 1) {
            unsigned long long v = __shfl_xor_sync(0xFFFFFFFFu, m, o);
            if (v < m) m = v;
        }
        if (t && lane == t - 1) myidx = (int)(unsigned)(m & 0xFFFFFFFFu);
        unsigned mask = __ballot_sync(0xFFFFFFFFu, cand == m);
        if (lane == __ffs(mask) - 1) {
            cand = (h < 32) ? sl[tid][h] : ~0ULL;
            h++;
        }
    }
    g_knn[(size_t)(b * NPT + s) * KNN + lane] = myidx;
}

// ---------------- layer 1: grouped gather + 3->64 conv, accumulate stats ----------------
// Output channel-major g_y1[c][pos].
__global__ void layer1_kernel(const float* __restrict__ xyz,
                              const float* __restrict__ newxyz,
                              const float* __restrict__ W1,
                              const float* __restrict__ b1) {
    __shared__ float4 zs[64];
    __shared__ float red[256], red2[256];
    const int tid = threadIdx.x;
    const int c = tid & 63, q = tid >> 6;
    const float w0 = W1[c * 3 + 0], w1 = W1[c * 3 + 1], w2 = W1[c * 3 + 2];
    const float bb = b1[c];
    float s = 0.f, s2 = 0.f;

    for (int tile = blockIdx.x; tile < NTILES; tile += gridDim.x) {
        int pbase = tile * 64;
        if (tid < 64) {
            int pos = pbase + tid;
            int bs = pos >> 5;           // b*1024 + s
            int b = bs >> 10;
            int j = g_knn[pos];
            const float* xp = xyz + (size_t)(b * NPTS + j) * 3;
            const float* np = newxyz + (size_t)bs * 3;
            zs[tid] = make_float4(xp[0] - np[0], xp[1] - np[1], xp[2] - np[2], 0.f);
        }
        __syncthreads();
        float acc[16];
#pragma unroll
        for (int u = 0; u < 16; u++) {
            float4 zv = zs[q * 16 + u];
            acc[u] = fmaf(w0, zv.x, fmaf(w1, zv.y, fmaf(w2, zv.z, bb)));
        }
        float* yo = g_y1 + (size_t)c * POSN + pbase + q * 16;
#pragma unroll
        for (int t = 0; t < 4; t++) {
            float4 v = make_float4(acc[4 * t], acc[4 * t + 1], acc[4 * t + 2], acc[4 * t + 3]);
            *(float4*)(yo + 4 * t) = v;
            s += v.x + v.y + v.z + v.w;
            s2 += v.x * v.x + v.y * v.y + v.z * v.z + v.w * v.w;
        }
        __syncthreads();
    }
    red[tid] = s; red2[tid] = s2;
    __syncthreads();
    if (tid < 128) { red[tid] += red[tid + 128]; red2[tid] += red2[tid + 128]; }
    __syncthreads();
    if (tid < 64) {
        atomicAdd(&g_sum[0][tid], (double)(red[tid] + red[tid + 64]));
        atomicAdd(&g_sqs[0][tid], (double)(red2[tid] + red2[tid + 64]));
    }
}

// ---------------- layers 2/3: BN+ReLU on load, 64->CO GEMM with f32x2 FMAs ----------------
// Shared tile: channel-major position-pairs; all GEMM loads are LDS.128 broadcast.
template <int CO>
__global__ void __launch_bounds__(256)
layer_kernel(const float* __restrict__ W, const float* __restrict__ bias) {
    constexpr int QP = (CO == 64) ? 16 : 32;   // positions per thread
    constexpr int PREV = (CO == 64) ? 0 : 1;
    constexpr int SELF = (CO == 64) ? 1 : 2;
    const float* yin = (CO == 64) ? g_y1 : g_y2;
    float* yout = (CO == 64) ? g_y2 : g_y3;

    __shared__ float2 zs2[64][34];             // [ch][pos-pair], padded
    __shared__ float ssc[64], ssh[64];
    __shared__ float red[256], red2[256];

    const int tid = threadIdx.x;
    const int c = tid & (CO - 1);
    const int q = tid / CO;

    if (tid < 64) { ssc[tid] = g_scale[PREV][tid]; ssh[tid] = g_shift[PREV][tid]; }

    float wr[64];
#pragma unroll
    for (int i = 0; i < 64; i++) wr[i] = W[c * 64 + i];
    const unsigned long long bb2 = f2pack(bias[c], bias[c]);
    float s = 0.f, s2 = 0.f;
    __syncthreads();

    for (int tile = blockIdx.x; tile < NTILES; tile += gridDim.x) {
        int pbase = tile * 64;
        // producer: load 64ch x 64pos, BN+ReLU, store channel-major pairs
#pragma unroll
        for (int rr = 0; rr < 4; rr++) {
            int e = tid + 256 * rr;            // 1024 float4 elements
            int ci = e >> 4, g = e & 15;
            float4 v = *(const float4*)(yin + (size_t)ci * POSN + pbase + 4 * g);
            float sc = ssc[ci], sh = ssh[ci];
            v.x = fmaxf(fmaf(v.x, sc, sh), 0.f);
            v.y = fmaxf(fmaf(v.y, sc, sh), 0.f);
            v.z = fmaxf(fmaf(v.z, sc, sh), 0.f);
            v.w = fmaxf(fmaf(v.w, sc, sh), 0.f);
            *(float4*)&zs2[ci][2 * g] = v;
        }
        __syncthreads();

        unsigned long long acc2[QP / 2];
#pragma unroll
        for (int m = 0; m < QP / 2; m++) acc2[m] = bb2;
#pragma unroll
        for (int ci = 0; ci < 64; ci++) {
            unsigned long long wp = f2pack(wr[ci], wr[ci]);
            const ulonglong2* zp = (const ulonglong2*)&zs2[ci][q * (QP / 2)];
#pragma unroll
            for (int g = 0; g < QP / 4; g++) {
                ulonglong2 z = zp[g];          // LDS.128 broadcast
                FMA2(acc2[2 * g],     wp, z.x, acc2[2 * g]);
                FMA2(acc2[2 * g + 1], wp, z.y, acc2[2 * g + 1]);
            }
        }

        float* yo = yout + (size_t)c * POSN + pbase + q * QP;
#pragma unroll
        for (int t = 0; t < QP / 4; t++) {
            float a0, a1, a2, a3;
            f2unpack(acc2[2 * t], a0, a1);
            f2unpack(acc2[2 * t + 1], a2, a3);
            *(float4*)(yo + 4 * t) = make_float4(a0, a1, a2, a3);
            s += a0 + a1 + a2 + a3;
            s2 += a0 * a0 + a1 * a1 + a2 * a2 + a3 * a3;
        }
        __syncthreads();
    }

    red[tid] = s; red2[tid] = s2;
    __syncthreads();
    if (CO == 64) {
        if (tid < 128) { red[tid] += red[tid + 128]; red2[tid] += red2[tid + 128]; }
        __syncthreads();
        if (tid < 64) {
            atomicAdd(&g_sum[SELF][tid], (double)(red[tid] + red[tid + 64]));
            atomicAdd(&g_sqs[SELF][tid], (double)(red2[tid] + red2[tid + 64]));
        }
    } else {
        if (tid < 128) {
            atomicAdd(&g_sum[SELF][tid], (double)(red[tid] + red[tid + 128]));
            atomicAdd(&g_sqs[SELF][tid], (double)(red2[tid] + red2[tid + 128]));
        }
    }
}

// ---------------- BN finalize: scale/shift per channel ----------------
__global__ void finalize_kernel(int l, const float* __restrict__ g,
                                const float* __restrict__ be, int C) {
    int c = threadIdx.x;
    if (c < C) {
        double n = (double)POSN;
        double m = g_sum[l][c] / n;
        double v = g_sqs[l][c] / n - m * m;
        if (v < 0.0) v = 0.0;
        float sc = g[c] * rsqrtf((float)v + 1e-5f);
        g_scale[l][c] = sc;
        g_shift[l][c] = be[c] - (float)m * sc;
    }
}

// ---------------- BN3 + ReLU + max-pool over K ----------------
// g_y3 channel-major: each thread reduces 32 consecutive floats; output coalesced.
__global__ void pool_kernel(float* __restrict__ out) {
    int gid = blockIdx.x * 256 + threadIdx.x;   // 16*128*1024 = 2097152 threads
    int s = gid & 1023;
    int bc = gid >> 10;
    int c = bc & 127, b = bc >> 7;
    const float sc = g_scale[2][c], sh = g_shift[2][c];
    const float4* base = (const float4*)(g_y3 + (size_t)c * POSN +
                                         (size_t)(b * NPT + s) * KNN);
    float m = 0.f;                               // == max over relu'd values
#pragma unroll
    for (int t = 0; t < 8; t++) {
        float4 v = base[t];
        m = fmaxf(m, fmaf(v.x, sc, sh));
        m = fmaxf(m, fmaf(v.y, sc, sh));
        m = fmaxf(m, fmaf(v.z, sc, sh));
        m = fmaxf(m, fmaf(v.w, sc, sh));
    }
    out[(size_t)(b * 128 + c) * NPT + s] = m;
}

// ---------------- launch ----------------
extern "C" void kernel_launch(void* const* d_in, const int* in_sizes, int n_in,
                              void* d_out, int out_size) {
    const float* xyz   = (const float*)d_in[0];
    const int*   initf = (const int*)d_in[1];
    const float* W1 = (const float*)d_in[2];
    const float* b1 = (const float*)d_in[3];
    const float* g1 = (const float*)d_in[4];
    const float* be1 = (const float*)d_in[5];
    const float* W2 = (const float*)d_in[6];
    const float* b2 = (const float*)d_in[7];
    const float* g2 = (const float*)d_in[8];
    const float* be2 = (const float*)d_in[9];
    const float* W3 = (const float*)d_in[10];
    const float* b3 = (const float*)d_in[11];
    const float* g3 = (const float*)d_in[12];
    const float* be3 = (const float*)d_in[13];

    float* out = (float*)d_out;
    float* newxyz = out;                               // [16,1024,3]
    float* newpts = out + (size_t)BATCH * NPT * 3;     // [16,128,1024]

    zero_stats_kernel<<<1, 384>>>();
    fps_kernel<<<BATCH, 256>>>(xyz, initf, newxyz);
    knn_kernel<<<BATCH * 256, 128>>>(newxyz);
    layer1_kernel<<<1024, 256>>>(xyz, newxyz, W1, b1);
    finalize_kernel<<<1, 128>>>(0, g1, be1, 64);
    layer_kernel<64><<<592, 256>>>(W2, b2);
    finalize_kernel<<<1, 128>>>(1, g2, be2, 64);
    layer_kernel<128><<<592, 256>>>(W3, b3);
    finalize_kernel<<<1, 128>>>(2, g3, be3, 128);
    pool_kernel<<<8192, 256>>>(newpts);
}